// round 14
// baseline (speedup 1.0000x reference)
#include <cuda_runtime.h>
#include <math.h>

// Problem constants
#define BB 32
#define TT 1000
#define DD 640
#define VV 1024
#define NB 128   // CTAs (<= 148 SMs -> all co-resident, sw grid barrier safe)
#define NT 512   // 16 warps per CTA (128 regs/thread cap)

typedef unsigned long long u64;

// ---------------- persistent device state (no allocations allowed) ----------
__device__ __align__(16) float g_hbuf[2][BB][DD];   // double-buffered h
__device__ __align__(16) float g_c[BB][DD];
__device__ __align__(16) float g_z[BB][DD];
__device__ __align__(16) float4 g_part[BB][NB];     // (max, sumexp, argmax, -) per CTA
__device__ float g_score[BB];
__device__ u64   g_bar = 0ull;                      // monotone barrier counter

// ---------------- grid barrier (counting, no reset; deterministic count per
// launch so graph replays stay consistent) ----------------------------------
__device__ __forceinline__ void grid_barrier() {
    __syncthreads();
    if (threadIdx.x == 0) {
        __threadfence();
        u64 m = atomicAdd(&g_bar, 1ull) + 1ull;
        u64 goal = ((m + (u64)NB - 1ull) / (u64)NB) * (u64)NB;
        while (*((volatile u64*)&g_bar) < goal) { }
        __threadfence();
    }
    __syncthreads();
}

__device__ __forceinline__ float wred(float v) {
    v += __shfl_xor_sync(0xffffffffu, v, 16);
    v += __shfl_xor_sync(0xffffffffu, v, 8);
    v += __shfl_xor_sync(0xffffffffu, v, 4);
    v += __shfl_xor_sync(0xffffffffu, v, 2);
    v += __shfl_xor_sync(0xffffffffu, v, 1);
    return v;
}

__device__ __forceinline__ float sigf(float x) { return 1.0f / (1.0f + expf(-x)); }

// Order-independent logsumexp/argmax merge (first-index on exact ties).
__device__ __forceinline__ void pmerge(float& m, float& s, int& mi,
                                       float m2, float s2, int i2) {
    if (m2 > m || (m2 == m && i2 < mi)) {
        s = s2 + s * expf(m - m2);
        m = m2; mi = i2;
    } else {
        s = s + s2 * expf(m2 - m);
    }
}

// ============================================================================
// Phase Z: z[b][j] = tanh( tn·W_tn + h·W_pn + b_joint ), CTA owns 5 j-cols.
// Warp = bgroup(4: 8 batches) x term(2) x k-half(2). acc[8][5].
// Weights loaded once per (bgroup, k-half) -> 4x duplication (was 16x).
// ============================================================================
__device__ __forceinline__ void z_phase(
    int cc, int wid, int lane, int t, int par,
    const float* __restrict__ tn, const float* __restrict__ W_tn,
    const float* __restrict__ W_pn, float zp[2][2][BB][5])
{
    const int j0   = cc * 5;
    const int bg   = wid >> 2;
    const int term = (wid >> 1) & 1;
    const int kh   = wid & 1;
    const int b0   = bg * 8;
    const float* __restrict__ W = term ? W_pn : W_tn;

    float acc[8][5];
#pragma unroll
    for (int i = 0; i < 8; i++)
#pragma unroll
        for (int j = 0; j < 5; j++) acc[i][j] = 0.f;

    // kh=0 -> kc {0,128,256}; kh=1 -> kc {384,512}
    for (int kc = kh ? 384 : 0; kc < (kh ? 640 : 384); kc += 128) {
        const int k = kc + lane * 4;
        float4 av[8];
#pragma unroll
        for (int i = 0; i < 8; i++) {
            av[i] = term
                ? *(const float4*)(&g_hbuf[par][b0 + i][k])
                : *(const float4*)(tn + ((size_t)(b0 + i) * TT + (size_t)t) * DD + k);
        }
#pragma unroll
        for (int j = 0; j < 5; j++) {
            float4 w = *(const float4*)(W + (size_t)(j0 + j) * DD + k);
#pragma unroll
            for (int i = 0; i < 8; i++) {
                float a = acc[i][j];
                a = fmaf(av[i].x, w.x, a); a = fmaf(av[i].y, w.y, a);
                a = fmaf(av[i].z, w.z, a); a = fmaf(av[i].w, w.w, a);
                acc[i][j] = a;
            }
        }
    }
#pragma unroll
    for (int i = 0; i < 8; i++)
#pragma unroll
        for (int j = 0; j < 5; j++) {
            float r = wred(acc[i][j]);
            if (lane == 0) zp[term][kh][b0 + i][j] = r;
        }
}

// Z combine: 160 threads -> z = tanh(sum of 4 partials + bias) -> g_z.
__device__ __forceinline__ void z_combine(
    int cc, int tid, const float* __restrict__ b_joint, float zp[2][2][BB][5])
{
    if (tid < BB * 5) {
        const int b = tid / 5, jj = tid - b * 5;
        const int j = cc * 5 + jj;
        g_z[b][j] = tanhf(zp[0][0][b][jj] + zp[0][1][b][jj] +
                          zp[1][0][b][jj] + zp[1][1][b][jj] + b_joint[j]);
    }
}

// ============================================================================
// Phase L: logits for CTA's 8 v-cols. Warp = bgroup(4) x v-half(2) x k-half(2),
// acc[8][4]. Partials to lv[kh]; combine does bias + 8-wide argmax/sumexp.
// ============================================================================
__device__ __forceinline__ void l_phase(
    int cc, int wid, int lane,
    const float* __restrict__ W_out, float lv[2][BB][8])
{
    const int bg = wid >> 2;
    const int vh = (wid >> 1) & 1;
    const int kh = wid & 1;
    const int b0 = bg * 8;
    const int v0 = cc * 8 + vh * 4;

    float acc[8][4];
#pragma unroll
    for (int i = 0; i < 8; i++)
#pragma unroll
        for (int v = 0; v < 4; v++) acc[i][v] = 0.f;

    for (int kc = kh ? 384 : 0; kc < (kh ? 640 : 384); kc += 128) {
        const int k = kc + lane * 4;
        float4 zv[8];
#pragma unroll
        for (int i = 0; i < 8; i++) zv[i] = *(const float4*)(&g_z[b0 + i][k]);
#pragma unroll
        for (int v = 0; v < 4; v++) {
            float4 w = *(const float4*)(W_out + (size_t)(v0 + v) * DD + k);
#pragma unroll
            for (int i = 0; i < 8; i++) {
                float a = acc[i][v];
                a = fmaf(zv[i].x, w.x, a); a = fmaf(zv[i].y, w.y, a);
                a = fmaf(zv[i].z, w.z, a); a = fmaf(zv[i].w, w.w, a);
                acc[i][v] = a;
            }
        }
    }
#pragma unroll
    for (int i = 0; i < 8; i++)
#pragma unroll
        for (int v = 0; v < 4; v++) {
            float r = wred(acc[i][v]);
            if (lane == 0) lv[kh][b0 + i][vh * 4 + v] = r;
        }
}

// L combine: threads 0-255: (b = tid/8, vs = tid%8); sum k-halves + bias,
// 8-wide shuffle argmax/logsumexp -> per-CTA partial into g_part.
__device__ __forceinline__ void l_combine(
    int cc, int tid, const float* __restrict__ b_out, float lv[2][BB][8])
{
    if (tid < BB * 8) {
        const int b = tid >> 3, vs = tid & 7;
        const int vabs = cc * 8 + vs;
        float val = lv[0][b][vs] + lv[1][b][vs] + b_out[vabs];

        float m = val; int mi = vabs;
#pragma unroll
        for (int d = 4; d > 0; d >>= 1) {
            float m2 = __shfl_xor_sync(0xffffffffu, m, d, 8);
            int   i2 = __shfl_xor_sync(0xffffffffu, mi, d, 8);
            if (m2 > m || (m2 == m && i2 < mi)) { m = m2; mi = i2; }
        }
        float s = expf(val - m);
#pragma unroll
        for (int d = 4; d > 0; d >>= 1)
            s += __shfl_xor_sync(0xffffffffu, s, d, 8);

        if (vs == 0) g_part[b][cc] = make_float4(m, s, (float)mi, 0.f);
    }
}

// ============================================================================
// Merge: warp wid merges the 128 partials for batches 2wid, 2wid+1 (bitwise-
// deterministic across CTAs); CTA 0 writes tokens + score.
// ============================================================================
__device__ __forceinline__ void merge_phase(
    int cc, int wid, int lane, int t,
    float* __restrict__ out, int* s_tok, int* s_nb)
{
#pragma unroll
    for (int bi = 0; bi < 2; bi++) {
        const int b = wid * 2 + bi;
        float4 q = g_part[b][lane];
        float m = q.x, s = q.y; int mi = (int)q.z;
#pragma unroll
        for (int r = 1; r < 4; r++) {
            float4 p = g_part[b][lane + 32 * r];
            pmerge(m, s, mi, p.x, p.y, (int)p.z);
        }
#pragma unroll
        for (int d = 16; d > 0; d >>= 1) {
            float m2 = __shfl_xor_sync(0xffffffffu, m, d);
            float s2 = __shfl_xor_sync(0xffffffffu, s, d);
            int   i2 = __shfl_xor_sync(0xffffffffu, mi, d);
            pmerge(m, s, mi, m2, s2, i2);
        }
        if (lane == 0) {
            const int nb = (mi != 0);
            s_nb[b] = nb;
            s_tok[b] = nb ? mi : 0;   // blank-step LSTM result is discarded
            if (cc == 0) {
                out[(size_t)b * TT + t] = nb ? (float)mi : 0.0f;
                if (nb) g_score[b] += -logf(s);  // logp at argmax
            }
        }
    }
}

// ============================================================================
// Phase G: LSTM gate GEMV. Warp = bgroup(4: 8 batches) x term(2) x pass(2),
// acc[8][10], full K in float2 chunks (keeps live regs under the 128 cap).
// term 0: E[tok]·W_ih -> sgx ; term 1: h·W_hh -> sgh.
// Weight rows loaded once per bgroup -> 4x duplication (was 8x).
// ============================================================================
__device__ __forceinline__ void g_phase(
    int cc, int wid, int lane, int rp,
    const float* __restrict__ E, const float* __restrict__ W_ih,
    const float* __restrict__ W_hh,
    float* sgx, float* sgh, const int* s_tok)
{
    const int j0   = cc * 5;
    const int bg   = wid >> 2;
    const int term = (wid >> 1) & 1;   // 0: x-half  1: h-half
    const int pass = wid & 1;          // 0: gates i,f   1: gates g,o
    const int b0   = bg * 8;
    const float* __restrict__ W = term ? W_hh : W_ih;

    float acc[8][10];
#pragma unroll
    for (int i = 0; i < 8; i++)
#pragma unroll
        for (int o = 0; o < 10; o++) acc[i][o] = 0.f;

    int xo[8];
#pragma unroll
    for (int i = 0; i < 8; i++) xo[i] = term ? 0 : s_tok[b0 + i] * DD;

#pragma unroll 1
    for (int kc = 0; kc < DD; kc += 64) {
        const int k = kc + lane * 2;
        float2 av[8];
#pragma unroll
        for (int i = 0; i < 8; i++) {
            av[i] = term ? *(const float2*)(&g_hbuf[rp][b0 + i][k])
                         : *(const float2*)(E + (size_t)xo[i] + k);
        }
#pragma unroll
        for (int o = 0; o < 10; o++) {
            const int row = (pass * 2 + o / 5) * DD + j0 + (o % 5);
            float2 w = *(const float2*)(W + (size_t)row * DD + k);
#pragma unroll
            for (int i = 0; i < 8; i++) {
                float a = acc[i][o];
                a = fmaf(av[i].x, w.x, a); a = fmaf(av[i].y, w.y, a);
                acc[i][o] = a;
            }
        }
    }

    float* sg = term ? sgh : sgx;
#pragma unroll
    for (int i = 0; i < 8; i++)
#pragma unroll
        for (int o = 0; o < 10; o++) {
            float r = wred(acc[i][o]);
            if (lane == 0) sg[(b0 + i) * 20 + pass * 10 + o] = r;
        }
}

// ============================================================================
// Pointwise LSTM update: warps 0-7, lanes 0-19 -> (batch, j) pairs.
// ============================================================================
__device__ __forceinline__ void pointwise(
    int cc, int wid, int lane, int rp,
    const float* __restrict__ b_lstm, const float* sgx, const float* sgh,
    const int* s_nb)
{
    const int j0 = cc * 5;
    if (wid < 8 && lane < 20) {
        const int i = lane / 5, jj = lane - i * 5;
        const int b = wid * 4 + i;
        const int j = j0 + jj;
        if (s_nb[b]) {
            float gi = sgx[b * 20 + jj]      + sgh[b * 20 + jj]      + b_lstm[j];
            float gf = sgx[b * 20 + 5 + jj]  + sgh[b * 20 + 5 + jj]  + b_lstm[DD + j];
            float gg = sgx[b * 20 + 10 + jj] + sgh[b * 20 + 10 + jj] + b_lstm[2 * DD + j];
            float go = sgx[b * 20 + 15 + jj] + sgh[b * 20 + 15 + jj] + b_lstm[3 * DD + j];
            float cn = sigf(gf) * g_c[b][j] + sigf(gi) * tanhf(gg);
            float hn = sigf(go) * tanhf(cn);
            g_c[b][j] = cn;
            g_hbuf[rp ^ 1][b][j] = hn;
        } else {
            g_hbuf[rp ^ 1][b][j] = g_hbuf[rp][b][j];
        }
    }
}

// ============================================================================
// Persistent kernel: init -> prime -> 1000 x { Z | L | merge, G, pointwise }
// ============================================================================
__global__ void __launch_bounds__(NT, 1)
rnnt_decode_kernel(const float* __restrict__ tn,     const float* __restrict__ E,
                   const float* __restrict__ W_ih,   const float* __restrict__ W_hh,
                   const float* __restrict__ b_lstm, const float* __restrict__ W_tn,
                   const float* __restrict__ W_pn,   const float* __restrict__ b_joint,
                   const float* __restrict__ W_out,  const float* __restrict__ b_out,
                   float* __restrict__ out)
{
    __shared__ float zp[2][2][BB][5];
    __shared__ float lv[2][BB][8];
    __shared__ float sgx[BB * 20];
    __shared__ float sgh[BB * 20];
    __shared__ int   s_tok[BB];
    __shared__ int   s_nb[BB];

    const int cc   = blockIdx.x;
    const int tid  = threadIdx.x;
    const int lane = tid & 31;
    const int wid  = tid >> 5;

    // ---- per-launch state init (deterministic across graph replays) ----
    for (int i = cc * NT + tid; i < BB * DD; i += NB * NT) {
        (&g_hbuf[0][0][0])[i] = 0.f;
        (&g_c[0][0])[i]       = 0.f;
    }
    if (cc == 0 && tid < BB) g_score[tid] = 0.f;
    grid_barrier();

    // ---- priming step: h,c = lstm(E[BLANK], 0, 0)  (h-term computes 0) ----
    if (wid == 0 && lane < BB) { s_tok[lane] = 0; s_nb[lane] = 1; }
    __syncthreads();
    int par = 0;
    g_phase(cc, wid, lane, par, E, W_ih, W_hh, sgx, sgh, s_tok);
    __syncthreads();
    pointwise(cc, wid, lane, par, b_lstm, sgx, sgh, s_nb);
    par = 1;
    grid_barrier();

    // ---- sequential decode ----
    for (int t = 0; t < TT; t++) {
        // Phase A: joint projection (batch-blocked, k-split), combine to g_z
        z_phase(cc, wid, lane, t, par, tn, W_tn, W_pn, zp);
        __syncthreads();
        z_combine(cc, tid, b_joint, zp);
        grid_barrier();

        // Phase B: logits GEMV (batch-blocked) + softmax partials
        l_phase(cc, wid, lane, W_out, lv);
        __syncthreads();
        l_combine(cc, tid, b_out, lv);
        grid_barrier();

        // Phase C: merge -> LSTM gates -> pointwise
        merge_phase(cc, wid, lane, t, out, s_tok, s_nb);
        __syncthreads();
        if (t < TT - 1) {
            g_phase(cc, wid, lane, par, E, W_ih, W_hh, sgx, sgh, s_tok);
            __syncthreads();
            pointwise(cc, wid, lane, par, b_lstm, sgx, sgh, s_nb);
            par ^= 1;
            grid_barrier();
        }
    }

    // ---- epilogue: scores + mean(exp(score)) (CTA 0 owns g_score) ----
    __syncthreads();
    if (cc == 0) {
        if (tid < BB) out[(size_t)BB * TT + tid] = g_score[tid];
        if (tid == 0) {
            float s = 0.f;
            for (int b = 0; b < BB; b++) s += expf(g_score[b]);
            out[(size_t)BB * TT + BB] = s / (float)BB;
        }
    }
}

extern "C" void kernel_launch(void* const* d_in, const int* in_sizes, int n_in,
                              void* d_out, int out_size)
{
    (void)in_sizes; (void)n_in; (void)out_size;
    const float* tn      = (const float*)d_in[0];
    const float* E       = (const float*)d_in[1];
    const float* W_ih    = (const float*)d_in[2];
    const float* W_hh    = (const float*)d_in[3];
    const float* b_lstm  = (const float*)d_in[4];
    const float* W_tn    = (const float*)d_in[5];
    const float* W_pn    = (const float*)d_in[6];
    const float* b_joint = (const float*)d_in[7];
    const float* W_out   = (const float*)d_in[8];
    const float* b_out   = (const float*)d_in[9];
    float* out = (float*)d_out;

    rnnt_decode_kernel<<<NB, NT>>>(tn, E, W_ih, W_hh, b_lstm,
                                   W_tn, W_pn, b_joint, W_out, b_out, out);
}

// round 15
// speedup vs baseline: 1.3758x; 1.3758x over previous
#include <cuda_runtime.h>
#include <math.h>

// Problem constants
#define BB 32
#define TT 1000
#define DD 640
#define VV 1024
#define NB 128   // CTAs (<= 148 SMs -> all co-resident, sw grid barrier safe)
#define NT 512   // 16 warps per CTA (128 regs/thread cap)

typedef unsigned long long u64;

// ---------------- persistent device state (no allocations allowed) ----------
__device__ __align__(16) float g_hbuf[2][BB][DD];   // double-buffered h
__device__ __align__(16) float g_c[BB][DD];
__device__ __align__(16) float g_z[BB][DD];
__device__ __align__(16) float4 g_part[BB][NB];     // (max, sumexp, argmax, -) per CTA
__device__ float g_score[BB];
__device__ u64   g_bar = 0ull;                      // monotone barrier counter

// ---------------- grid barrier (counting, no reset; deterministic count per
// launch so graph replays stay consistent) ----------------------------------
__device__ __forceinline__ void grid_barrier() {
    __syncthreads();
    if (threadIdx.x == 0) {
        __threadfence();
        u64 m = atomicAdd(&g_bar, 1ull) + 1ull;
        u64 goal = ((m + (u64)NB - 1ull) / (u64)NB) * (u64)NB;
        while (*((volatile u64*)&g_bar) < goal) { }
        __threadfence();
    }
    __syncthreads();
}

__device__ __forceinline__ float wred(float v) {
    v += __shfl_xor_sync(0xffffffffu, v, 16);
    v += __shfl_xor_sync(0xffffffffu, v, 8);
    v += __shfl_xor_sync(0xffffffffu, v, 4);
    v += __shfl_xor_sync(0xffffffffu, v, 2);
    v += __shfl_xor_sync(0xffffffffu, v, 1);
    return v;
}

// ---------------- multi-value tree reductions ------------------------------
// tred32: reduce v[0..31] across 32 lanes; afterwards lane l holds the full
// 32-lane sum of v[l]. ~4 instr per surviving value per stage.
__device__ __forceinline__ float tred32(float* v, int lane) {
#pragma unroll
    for (int s = 0; s < 5; s++) {
        const int d = 16 >> s;
#pragma unroll
        for (int i = 0; i < 16; i++) {
            if (i < d) {
                float lo = v[i], hi = v[i + d];
                float send = (lane & d) ? lo : hi;
                float recv = __shfl_xor_sync(0xffffffffu, send, d);
                v[i] = ((lane & d) ? hi : lo) + recv;
            }
        }
    }
    return v[0];
}

// tred16: reduce v[0..15]; lane l holds sum of value ((l>>1)&15), duplicated
// in lane pairs {2k, 2k+1}.
__device__ __forceinline__ float tred16(float* v, int lane) {
#pragma unroll
    for (int s = 0; s < 4; s++) {
        const int d = 16 >> s;        // 16,8,4,2
        const int r = 8 >> s;         // 8,4,2,1
#pragma unroll
        for (int i = 0; i < 8; i++) {
            if (i < r) {
                float lo = v[i], hi = v[i + r];
                float send = (lane & d) ? lo : hi;
                float recv = __shfl_xor_sync(0xffffffffu, send, d);
                v[i] = ((lane & d) ? hi : lo) + recv;
            }
        }
    }
    float x = v[0];
    x += __shfl_xor_sync(0xffffffffu, x, 1);
    return x;                         // idx = (lane >> 1) & 15
}

// tred8: reduce v[0..7]; lane l holds sum of value ((l>>2)&7), duplicated x4.
__device__ __forceinline__ float tred8(float* v, int lane) {
#pragma unroll
    for (int s = 0; s < 3; s++) {
        const int d = 16 >> s;        // 16,8,4
        const int r = 4 >> s;         // 4,2,1
#pragma unroll
        for (int i = 0; i < 4; i++) {
            if (i < r) {
                float lo = v[i], hi = v[i + r];
                float send = (lane & d) ? lo : hi;
                float recv = __shfl_xor_sync(0xffffffffu, send, d);
                v[i] = ((lane & d) ? hi : lo) + recv;
            }
        }
    }
    float x = v[0];
    x += __shfl_xor_sync(0xffffffffu, x, 2);
    x += __shfl_xor_sync(0xffffffffu, x, 1);
    return x;                         // idx = (lane >> 2) & 7
}

__device__ __forceinline__ float sigf(float x) { return 1.0f / (1.0f + expf(-x)); }

// Order-independent logsumexp/argmax merge (first-index on exact ties).
__device__ __forceinline__ void pmerge(float& m, float& s, int& mi,
                                       float m2, float s2, int i2) {
    if (m2 > m || (m2 == m && i2 < mi)) {
        s = s2 + s * expf(m - m2);
        m = m2; mi = i2;
    } else {
        s = s + s2 * expf(m2 - m);
    }
}

// ============================================================================
// Phase Z: z[b][j] = tanh( tn[b][t]·W_tn[j] + h[b]·W_pn[j] + b_joint[j] )
// 16 warps: warp owns 2 batches; CTA owns 5 j-columns; lanes split K (float4).
// Tail: tred8 (8 values, parallel tanh+store) + 2 classic wred.
// ============================================================================
__device__ __forceinline__ void z_phase(
    int cc, int wid, int lane, int t, int par,
    const float* __restrict__ tn, const float* __restrict__ W_tn,
    const float* __restrict__ W_pn, const float* __restrict__ b_joint)
{
    const int j0 = cc * 5;
    const int b0 = wid * 2;
    float acc[2][5];
#pragma unroll
    for (int i = 0; i < 2; i++)
#pragma unroll
        for (int j = 0; j < 5; j++) acc[i][j] = 0.f;

    for (int kc = 0; kc < DD; kc += 128) {
        const int k = kc + lane * 4;
        float4 a1[2], a2[2];
#pragma unroll
        for (int i = 0; i < 2; i++) {
            a1[i] = *(const float4*)(tn + ((size_t)(b0 + i) * TT + (size_t)t) * DD + k);
            a2[i] = *(const float4*)(&g_hbuf[par][b0 + i][k]);
        }
#pragma unroll
        for (int j = 0; j < 5; j++) {
            float4 w1 = *(const float4*)(W_tn + (size_t)(j0 + j) * DD + k);
            float4 w2 = *(const float4*)(W_pn + (size_t)(j0 + j) * DD + k);
#pragma unroll
            for (int i = 0; i < 2; i++) {
                float a = acc[i][j];
                a = fmaf(a1[i].x, w1.x, a); a = fmaf(a1[i].y, w1.y, a);
                a = fmaf(a1[i].z, w1.z, a); a = fmaf(a1[i].w, w1.w, a);
                a = fmaf(a2[i].x, w2.x, a); a = fmaf(a2[i].y, w2.y, a);
                a = fmaf(a2[i].z, w2.z, a); a = fmaf(a2[i].w, w2.w, a);
                acc[i][j] = a;
            }
        }
    }
    // tail: flat fi = i*5 + j; tred8 covers fi 0..7, wred the last 2
    float* af = &acc[0][0];
    float r2a = wred(af[8]);           // (i=1, j=3)
    float r2b = wred(af[9]);           // (i=1, j=4)
    float r8  = tred8(af, lane);       // lane holds fi = (lane>>2)&7
    {
        const int fi = (lane >> 2) & 7;
        const int i = fi / 5, j = fi - i * 5;
        if ((lane & 3) == 0)
            g_z[b0 + i][j0 + j] = tanhf(r8 + b_joint[j0 + j]);
    }
    if (lane == 0) {
        g_z[b0 + 1][j0 + 3] = tanhf(r2a + b_joint[j0 + 3]);
        g_z[b0 + 1][j0 + 4] = tanhf(r2b + b_joint[j0 + 4]);
    }
}

// ============================================================================
// Phase L: logits for CTA's 8 v-columns; emit (max, sumexp, argmax) partial
// per (batch, CTA). Warp owns 2 batches. Tail: tred16, then parallel 3-stage
// butterfly argmax/logsumexp over the v dimension; lanes 0/16 write g_part.
// ============================================================================
__device__ __forceinline__ void l_phase(
    int cc, int wid, int lane,
    const float* __restrict__ W_out, const float* __restrict__ b_out)
{
    const int v0 = cc * 8;
    const int b0 = wid * 2;
    float acc[2][8];
#pragma unroll
    for (int i = 0; i < 2; i++)
#pragma unroll
        for (int v = 0; v < 8; v++) acc[i][v] = 0.f;

    for (int kc = 0; kc < DD; kc += 128) {
        const int k = kc + lane * 4;
        float4 zv[2];
#pragma unroll
        for (int i = 0; i < 2; i++) zv[i] = *(const float4*)(&g_z[b0 + i][k]);
#pragma unroll
        for (int v = 0; v < 8; v++) {
            float4 wv = *(const float4*)(W_out + (size_t)(v0 + v) * DD + k);
#pragma unroll
            for (int i = 0; i < 2; i++) {
                float a = acc[i][v];
                a = fmaf(zv[i].x, wv.x, a); a = fmaf(zv[i].y, wv.y, a);
                a = fmaf(zv[i].z, wv.z, a); a = fmaf(zv[i].w, wv.w, a);
                acc[i][v] = a;
            }
        }
    }
    // tred16: lane holds flat idx = (lane>>1)&15 = i*8 + v (dup in lane pairs)
    float tv = tred16(&acc[0][0], lane);
    const int idx = (lane >> 1) & 15;
    const int v = idx & 7;
    const int vabs = v0 + v;
    float val = tv + b_out[vabs];

    // group max/argmax over v (lanes l, l^8, l^4, l^2 span v^{4,2,1})
    float m = val; int mi = vabs;
#pragma unroll
    for (int d = 8; d >= 2; d >>= 1) {
        float m2 = __shfl_xor_sync(0xffffffffu, m, d);
        int   i2 = __shfl_xor_sync(0xffffffffu, mi, d);
        if (m2 > m || (m2 == m && i2 < mi)) { m = m2; mi = i2; }
    }
    float s = expf(val - m);
#pragma unroll
    for (int d = 8; d >= 2; d >>= 1)
        s += __shfl_xor_sync(0xffffffffu, s, d);

    if ((lane & 15) == 0)
        g_part[b0 + (lane >> 4)][cc] = make_float4(m, s, (float)mi, 0.f);
}

// ============================================================================
// Phase CG: (a) every CTA redundantly merges the 128 partials per batch
// (bitwise-deterministic) -> smem tok/nonblank; CTA 0 writes tokens + score.
// (b) LSTM gates GEMV: warps 0-7 gates {i,f}, warps 8-15 gates {g,o}, each
// warp 4 batches x 10 rows, both matrices in one K loop. Tail: tred32+tred8
// with fully parallel smem stores.
// ============================================================================
__device__ __forceinline__ void cg_phase(
    int cc, int wid, int lane, int t, int rp, int prime, int do_lstm,
    const float* __restrict__ E, const float* __restrict__ W_ih,
    const float* __restrict__ W_hh, const float* __restrict__ b_lstm,
    float* __restrict__ out, float* sg, int* s_tok, int* s_nb)
{
    if (!prime) {
        // warp wid merges partials for batches 2*wid, 2*wid+1
#pragma unroll
        for (int bi = 0; bi < 2; bi++) {
            const int b = wid * 2 + bi;
            float4 q = g_part[b][lane];
            float m = q.x, s = q.y; int mi = (int)q.z;
#pragma unroll
            for (int r = 1; r < 4; r++) {
                float4 p = g_part[b][lane + 32 * r];
                pmerge(m, s, mi, p.x, p.y, (int)p.z);
            }
#pragma unroll
            for (int d = 16; d > 0; d >>= 1) {
                float m2 = __shfl_xor_sync(0xffffffffu, m, d);
                float s2 = __shfl_xor_sync(0xffffffffu, s, d);
                int   i2 = __shfl_xor_sync(0xffffffffu, mi, d);
                pmerge(m, s, mi, m2, s2, i2);
            }
            if (lane == 0) {
                const int nb = (mi != 0);
                s_nb[b] = nb;
                s_tok[b] = nb ? mi : 0;   // blank-step LSTM result is discarded
                if (cc == 0) {
                    out[(size_t)b * TT + t] = nb ? (float)mi : 0.0f;
                    if (nb) g_score[b] += -logf(s);  // logp at argmax
                }
            }
        }
    } else {
        if (wid == 0) { s_tok[lane] = 0; s_nb[lane] = 1; }
    }
    __syncthreads();
    if (!do_lstm) return;

    const int j0 = cc * 5;
    const int pass = wid >> 3;          // 0: gates i,f   1: gates g,o
    const int b0 = (wid & 7) * 4;
    float acc[4][10];
#pragma unroll
    for (int i = 0; i < 4; i++)
#pragma unroll
        for (int o = 0; o < 10; o++) acc[i][o] = 0.f;

    const float* xp[4];
#pragma unroll
    for (int i = 0; i < 4; i++) xp[i] = E + (size_t)s_tok[b0 + i] * DD;

#pragma unroll 1
    for (int kc = 0; kc < DD; kc += 128) {
        const int k = kc + lane * 4;
        float4 xv[4], hv[4];
#pragma unroll
        for (int i = 0; i < 4; i++) {
            xv[i] = *(const float4*)(xp[i] + k);
            hv[i] = *(const float4*)(&g_hbuf[rp][b0 + i][k]);
        }
#pragma unroll
        for (int o = 0; o < 10; o++) {
            const int row = (pass * 2 + o / 5) * DD + j0 + (o % 5);
            float4 wi = *(const float4*)(W_ih + (size_t)row * DD + k);
            float4 wh = *(const float4*)(W_hh + (size_t)row * DD + k);
#pragma unroll
            for (int i = 0; i < 4; i++) {
                float a = acc[i][o];
                a = fmaf(xv[i].x, wi.x, a); a = fmaf(xv[i].y, wi.y, a);
                a = fmaf(xv[i].z, wi.z, a); a = fmaf(xv[i].w, wi.w, a);
                a = fmaf(hv[i].x, wh.x, a); a = fmaf(hv[i].y, wh.y, a);
                a = fmaf(hv[i].z, wh.z, a); a = fmaf(hv[i].w, wh.w, a);
                acc[i][o] = a;
            }
        }
    }
    // tail: flat fi = i*10 + o; tred32 covers fi 0..31, tred8 covers 32..39
    {
        float* af = &acc[0][0];
        float r32 = tred32(af, lane);          // lane holds fi = lane
        float r8  = tred8(af + 32, lane);      // holds fi = 32 + (lane>>2)&7
        {
            const int i = lane / 10, o = lane - i * 10;
            sg[(b0 + i) * 20 + pass * 10 + o] = r32;   // all 32 lanes store
        }
        if ((lane & 3) == 0) {
            const int o = 2 + ((lane >> 2) & 7);       // fi 32..39 -> (i=3, o=2..9)
            sg[(b0 + 3) * 20 + pass * 10 + o] = r8;
        }
    }
    __syncthreads();

    // pointwise LSTM update: warps 0-7, lanes 0-19 -> (batch, j) pairs
    if (wid < 8 && lane < 20) {
        const int i = lane / 5, jj = lane - i * 5;
        const int b = wid * 4 + i;
        const int j = j0 + jj;
        if (s_nb[b]) {
            float gi = sg[b * 20 + jj]      + b_lstm[j];
            float gf = sg[b * 20 + 5 + jj]  + b_lstm[DD + j];
            float gg = sg[b * 20 + 10 + jj] + b_lstm[2 * DD + j];
            float go = sg[b * 20 + 15 + jj] + b_lstm[3 * DD + j];
            float cn = sigf(gf) * g_c[b][j] + sigf(gi) * tanhf(gg);
            float hn = sigf(go) * tanhf(cn);
            g_c[b][j] = cn;
            g_hbuf[rp ^ 1][b][j] = hn;
        } else {
            g_hbuf[rp ^ 1][b][j] = g_hbuf[rp][b][j];
        }
    }
}

// ============================================================================
// Persistent kernel: init -> prime LSTM -> 1000 x {Z | L | CG} (3 barriers/step)
// ============================================================================
__global__ void __launch_bounds__(NT, 1)
rnnt_decode_kernel(const float* __restrict__ tn,     const float* __restrict__ E,
                   const float* __restrict__ W_ih,   const float* __restrict__ W_hh,
                   const float* __restrict__ b_lstm, const float* __restrict__ W_tn,
                   const float* __restrict__ W_pn,   const float* __restrict__ b_joint,
                   const float* __restrict__ W_out,  const float* __restrict__ b_out,
                   float* __restrict__ out)
{
    __shared__ float sg[BB * 20];
    __shared__ int   s_tok[BB];
    __shared__ int   s_nb[BB];

    const int cc   = blockIdx.x;
    const int tid  = threadIdx.x;
    const int lane = tid & 31;
    const int wid  = tid >> 5;

    // ---- per-launch state init (deterministic across graph replays) ----
    for (int i = cc * NT + tid; i < BB * DD; i += NB * NT) {
        (&g_hbuf[0][0][0])[i] = 0.f;
        (&g_c[0][0])[i]       = 0.f;
    }
    if (cc == 0 && tid < BB) g_score[tid] = 0.f;
    grid_barrier();

    // ---- priming LSTM step: h,c = lstm(E[BLANK], 0, 0) ----
    int par = 0;
    cg_phase(cc, wid, lane, 0, par, /*prime=*/1, /*do_lstm=*/1,
             E, W_ih, W_hh, b_lstm, out, sg, s_tok, s_nb);
    par ^= 1;
    grid_barrier();

    // ---- sequential decode ----
    for (int t = 0; t < TT; t++) {
        z_phase(cc, wid, lane, t, par, tn, W_tn, W_pn, b_joint);
        grid_barrier();
        l_phase(cc, wid, lane, W_out, b_out);
        grid_barrier();
        cg_phase(cc, wid, lane, t, par, /*prime=*/0,
                 /*do_lstm=*/(t < TT - 1) ? 1 : 0,
                 E, W_ih, W_hh, b_lstm, out, sg, s_tok, s_nb);
        if (t < TT - 1) { par ^= 1; grid_barrier(); }
    }

    // ---- epilogue: scores + mean(exp(score)) (CTA 0 owns g_score) ----
    __syncthreads();
    if (cc == 0) {
        if (tid < BB) out[(size_t)BB * TT + tid] = g_score[tid];
        if (tid == 0) {
            float s = 0.f;
            for (int b = 0; b < BB; b++) s += expf(g_score[b]);
            out[(size_t)BB * TT + BB] = s / (float)BB;
        }
    }
}

extern "C" void kernel_launch(void* const* d_in, const int* in_sizes, int n_in,
                              void* d_out, int out_size)
{
    (void)in_sizes; (void)n_in; (void)out_size;
    const float* tn      = (const float*)d_in[0];
    const float* E       = (const float*)d_in[1];
    const float* W_ih    = (const float*)d_in[2];
    const float* W_hh    = (const float*)d_in[3];
    const float* b_lstm  = (const float*)d_in[4];
    const float* W_tn    = (const float*)d_in[5];
    const float* W_pn    = (const float*)d_in[6];
    const float* b_joint = (const float*)d_in[7];
    const float* W_out   = (const float*)d_in[8];
    const float* b_out   = (const float*)d_in[9];
    float* out = (float*)d_out;

    rnnt_decode_kernel<<<NB, NT>>>(tn, E, W_ih, W_hh, b_lstm,
                                   W_tn, W_pn, b_joint, W_out, b_out, out);
}